// round 1
// baseline (speedup 1.0000x reference)
#include <cuda_runtime.h>
#include <math.h>

#define HID 128
#define NTHREADS 256
#define NBLOCKS 592

// Shared-memory layout (floats):
//  sW1: 7*128   sb1: 128   sW2: 128*128   sb2: 128   sW3: 128*4   sb3: 4
#define SMEM_FLOATS (7*HID + HID + HID*HID + HID + HID*4 + 4)

__global__ __launch_bounds__(NTHREADS)
void defcorr_kernel(const float* __restrict__ Fg,
                    const float* __restrict__ W1, const float* __restrict__ b1,
                    const float* __restrict__ W2, const float* __restrict__ b2,
                    const float* __restrict__ W3, const float* __restrict__ b3,
                    float* __restrict__ out, int n)
{
    extern __shared__ float smem[];
    float* sW1 = smem;               // [7][128]
    float* sb1 = sW1 + 7*HID;        // [128]
    float* sW2 = sb1 + HID;          // [128][128]
    float* sb2 = sW2 + HID*HID;      // [128]
    float* sW3 = sb2 + HID;          // [128][4]
    float* sb3 = sW3 + HID*4;        // [4]

    const int tid = threadIdx.x;
    for (int i = tid; i < 7*HID; i += NTHREADS)   sW1[i] = W1[i];
    for (int i = tid; i < HID;   i += NTHREADS) { sb1[i] = b1[i]; sb2[i] = b2[i]; }
    for (int i = tid; i < HID*HID; i += NTHREADS) sW2[i] = W2[i];
    for (int i = tid; i < HID*4; i += NTHREADS)   sW3[i] = W3[i];
    if (tid < 4) sb3[tid] = b3[tid];
    __syncthreads();

    for (int idx = blockIdx.x * NTHREADS + tid; idx < n; idx += gridDim.x * NTHREADS) {
        const float4 f = reinterpret_cast<const float4*>(Fg)[idx];
        const float a = f.x, b = f.y, c = f.z, d = f.w;

        // ---- closed-form 2x2 SVD invariants + polar rotation ----
        const float t0 = a + d;   // trace
        const float t1 = b - c;   // antisymmetric part
        const float t2 = a - d;
        const float t3 = b + c;
        const float p = sqrtf(t0*t0 + t1*t1);
        const float q = sqrtf(t2*t2 + t3*t3);
        const float s1 = 0.5f * (p + q);
        const float s2 = 0.5f * fabsf(p - q);
        const float det = a*d - b*c;

        float inv[7];
        inv[0] = s1 - 1.0f;
        inv[1] = s2 - 1.0f;
        inv[2] = a*a + c*c - 1.0f;   // (F^T F)[0][0] - 1
        inv[3] = a*b + c*d;          // (F^T F)[0][1]
        inv[4] = inv[3];             // (F^T F)[1][0]
        inv[5] = b*b + d*d - 1.0f;   // (F^T F)[1][1] - 1
        inv[6] = det - 1.0f;

        // R = U Vh (polar rotation, valid for det>0 which holds for this data)
        const float rp  = 1.0f / p;
        const float r00 = t0 * rp;
        const float r01 = t1 * rp;
        const float r10 = -t1 * rp;
        const float r11 = t0 * rp;

        // ---- MLP: layer2 accumulators in registers, h1 computed on the fly ----
        float acc[HID];
        #pragma unroll
        for (int j = 0; j < HID; j++) acc[j] = sb2[j];

        for (int k = 0; k < HID; k++) {
            float h = sb1[k];
            #pragma unroll
            for (int i = 0; i < 7; i++) h = fmaf(inv[i], sW1[i*HID + k], h);
            h = fmaxf(h, 0.0f);

            const float4* wrow = reinterpret_cast<const float4*>(sW2 + k*HID);
            #pragma unroll
            for (int j = 0; j < HID/4; j++) {
                const float4 w = wrow[j];             // broadcast LDS.128
                acc[4*j+0] = fmaf(h, w.x, acc[4*j+0]);
                acc[4*j+1] = fmaf(h, w.y, acc[4*j+1]);
                acc[4*j+2] = fmaf(h, w.z, acc[4*j+2]);
                acc[4*j+3] = fmaf(h, w.w, acc[4*j+3]);
            }
        }

        // ---- layer 3: 128 -> 4 ----
        float o0 = sb3[0], o1 = sb3[1], o2 = sb3[2], o3 = sb3[3];
        #pragma unroll
        for (int k = 0; k < HID; k++) {
            const float h = fmaxf(acc[k], 0.0f);
            const float4 w = reinterpret_cast<const float4*>(sW3)[k];  // broadcast
            o0 = fmaf(h, w.x, o0);
            o1 = fmaf(h, w.y, o1);
            o2 = fmaf(h, w.z, o2);
            o3 = fmaf(h, w.w, o3);
        }

        // ---- symmetrize, rotate, add F ----
        const float x00 = o0;
        const float x01 = 0.5f * (o1 + o2);
        const float x11 = o3;

        const float d00 = r00*x00 + r01*x01;
        const float d01 = r00*x01 + r01*x11;
        const float d10 = r10*x00 + r11*x01;
        const float d11 = r10*x01 + r11*x11;

        float4 ov;
        ov.x = d00 + a;
        ov.y = d01 + b;
        ov.z = d10 + c;
        ov.w = d11 + d;
        reinterpret_cast<float4*>(out)[idx] = ov;
    }
}

extern "C" void kernel_launch(void* const* d_in, const int* in_sizes, int n_in,
                              void* d_out, int out_size)
{
    const float* F  = (const float*)d_in[0];
    const float* W1 = (const float*)d_in[1];
    const float* b1 = (const float*)d_in[2];
    const float* W2 = (const float*)d_in[3];
    const float* b2 = (const float*)d_in[4];
    const float* W3 = (const float*)d_in[5];
    const float* b3 = (const float*)d_in[6];
    float* out = (float*)d_out;

    const int n = in_sizes[0] / 4;   // number of 2x2 matrices

    const size_t smem_bytes = SMEM_FLOATS * sizeof(float);  // ~72 KB > 48 KB default
    cudaFuncSetAttribute(defcorr_kernel,
                         cudaFuncAttributeMaxDynamicSharedMemorySize,
                         (int)smem_bytes);

    defcorr_kernel<<<NBLOCKS, NTHREADS, smem_bytes>>>(F, W1, b1, W2, b2, W3, b3, out, n);
}

// round 3
// speedup vs baseline: 14.5629x; 14.5629x over previous
#include <cuda_runtime.h>
#include <cuda_fp16.h>
#include <cstdint>

#define NTHREADS 256
#define NBLOCKS  148

// ---------------- PTX helpers ----------------
__device__ __forceinline__ uint32_t smem_u32(const void* p) {
    uint32_t a;
    asm("{ .reg .u64 t; cvta.to.shared.u64 t, %1; cvt.u32.u64 %0, t; }" : "=r"(a) : "l"(p));
    return a;
}
__device__ __forceinline__ void ldmx2(uint32_t& r0, uint32_t& r1, uint32_t addr) {
    asm volatile("ldmatrix.sync.aligned.m8n8.x2.shared.b16 {%0,%1}, [%2];"
                 : "=r"(r0), "=r"(r1) : "r"(addr));
}
__device__ __forceinline__ void ldmx4(uint32_t& r0, uint32_t& r1, uint32_t& r2, uint32_t& r3,
                                      uint32_t addr) {
    asm volatile("ldmatrix.sync.aligned.m8n8.x4.shared.b16 {%0,%1,%2,%3}, [%4];"
                 : "=r"(r0), "=r"(r1), "=r"(r2), "=r"(r3) : "r"(addr));
}
__device__ __forceinline__ void mma_k8(float* d, uint32_t a0, uint32_t a1, uint32_t b0) {
    asm volatile("mma.sync.aligned.m16n8k8.row.col.f32.f16.f16.f32 "
                 "{%0,%1,%2,%3}, {%4,%5}, {%6}, {%0,%1,%2,%3};"
                 : "+f"(d[0]), "+f"(d[1]), "+f"(d[2]), "+f"(d[3])
                 : "r"(a0), "r"(a1), "r"(b0));
}
__device__ __forceinline__ void mma_k16(float* d, uint32_t a0, uint32_t a1, uint32_t a2,
                                        uint32_t a3, uint32_t b0, uint32_t b1) {
    asm volatile("mma.sync.aligned.m16n8k16.row.col.f32.f16.f16.f32 "
                 "{%0,%1,%2,%3}, {%4,%5,%6,%7}, {%8,%9}, {%0,%1,%2,%3};"
                 : "+f"(d[0]), "+f"(d[1]), "+f"(d[2]), "+f"(d[3])
                 : "r"(a0), "r"(a1), "r"(a2), "r"(a3), "r"(b0), "r"(b1));
}
__device__ __forceinline__ uint32_t pack_h2(float x, float y) {
    __half2 h = __floats2half2_rn(x, y);          // low half = x
    return *reinterpret_cast<uint32_t*>(&h);
}

// ---------------- shared memory ----------------
struct SmemT {
    __align__(16) uint8_t w2t[128 * 256];   // W2^T [n][k] half, swizzled 256B rows (32 KB)
    __align__(16) __half  w1t[128 * 8];     // W1^T [n][k0..6], k7 = b1[n]          (2 KB)
    __align__(16) __half  inv[128 * 8];     // per-row invariants (k7 = 1.0)        (2 KB)
    __align__(16) float   scal[128 * 8];    // per-row {a,b,c,d,r00,r01,-,-}        (4 KB)
    __align__(16) float   w3[128 * 4];      // W3 rows as float4                    (2 KB)
    float b2[128];
    float b3[4];
};

__global__ __launch_bounds__(NTHREADS, 1)
void defcorr_mma(const float* __restrict__ Fg,
                 const float* __restrict__ W1, const float* __restrict__ b1,
                 const float* __restrict__ W2, const float* __restrict__ b2,
                 const float* __restrict__ W3, const float* __restrict__ b3,
                 float* __restrict__ out, int n)
{
    __shared__ SmemT sm;

    const int tid  = threadIdx.x;
    const int lane = tid & 31;
    const int warp = tid >> 5;
    const int warpm = warp * 16;              // this warp's m-tile base row

    // ---------- stage weights (once) ----------
    // W2^T: [n][k] half; chunk swizzle c' = (c&8) | ((c ^ n) & 7), 16B chunks, 256B rows
    for (int i = tid; i < 128 * 128; i += NTHREADS) {
        const int nn = i >> 7, k = i & 127;
        const int c  = k >> 3;
        const int cs = (c & 8) | ((c ^ nn) & 7);
        const uint32_t off = (uint32_t)nn * 256u + (uint32_t)cs * 16u + (uint32_t)(k & 7) * 2u;
        *reinterpret_cast<__half*>(sm.w2t + off) = __float2half(W2[k * 128 + nn]);
    }
    for (int i = tid; i < 128 * 8; i += NTHREADS) {
        const int nn = i >> 3, k = i & 7;
        sm.w1t[i] = __float2half(k < 7 ? W1[k * 128 + nn] : b1[nn]);
    }
    for (int i = tid; i < 128 * 4; i += NTHREADS) sm.w3[i] = W3[i];
    for (int i = tid; i < 128;     i += NTHREADS) sm.b2[i] = b2[i];
    if (tid < 4) sm.b3[tid] = b3[tid];
    __syncthreads();

    const uint32_t uW2  = smem_u32(sm.w2t);
    const uint32_t uW1  = smem_u32(sm.w1t);
    const uint32_t uInv = smem_u32(sm.inv);

    // ---------- preload layer-1 B fragments (constant for whole kernel) ----------
    // b1f[j] = b0 of n-tile j (k0..7). ldmatrix.x4 q loads tiles 4q..4q+3; lane addr row = 32q+lane.
    uint32_t b1f[16];
    #pragma unroll
    for (int q = 0; q < 4; ++q)
        ldmx4(b1f[4*q], b1f[4*q+1], b1f[4*q+2], b1f[4*q+3],
              uW1 + (uint32_t)(q * 32 + lane) * 16u);

    // per-lane layer-2 ldmatrix address components
    const int rowPart = ((lane >> 4) << 3) | (lane & 7);  // n within 16-row group
    const int kSel    = (lane >> 3) & 1;                  // 0: k-lo chunk, 1: k-hi chunk
    const uint32_t bAddrBase = uW2 + (uint32_t)rowPart * 256u;

    const int ntiles = (n + 127) >> 7;

    for (int tile = blockIdx.x; tile < ntiles; tile += gridDim.x) {
        __syncthreads();   // protect inv/scal reuse across iterations

        // ---------- per-row invariants (threads 0..127) ----------
        if (tid < 128) {
            const int row  = tid;
            const int elem = tile * 128 + row;
            float a = 1.f, b = 0.f, c = 0.f, d = 1.f;
            if (elem < n) {
                const float4 f = reinterpret_cast<const float4*>(Fg)[elem];
                a = f.x; b = f.y; c = f.z; d = f.w;
            }
            const float t0 = a + d, t1 = b - c, t2 = a - d, t3 = b + c;
            const float p = sqrtf(t0*t0 + t1*t1);
            const float q = sqrtf(t2*t2 + t3*t3);
            const float i0 = 0.5f*(p + q) - 1.f;
            const float i1 = 0.5f*fabsf(p - q) - 1.f;
            const float i2 = a*a + c*c - 1.f;
            const float i3 = a*b + c*d;          // == i4
            const float i5 = b*b + d*d - 1.f;
            const float i6 = a*d - b*c - 1.f;
            const float rp  = 1.f / p;
            const float r00 = t0 * rp, r01 = t1 * rp;

            uint4 u;
            u.x = pack_h2(i0, i1);
            u.y = pack_h2(i2, i3);
            u.z = pack_h2(i3, i5);
            u.w = pack_h2(i6, 1.0f);             // k7 = 1.0 (bias input)
            reinterpret_cast<uint4*>(sm.inv)[row] = u;

            float4* s = reinterpret_cast<float4*>(sm.scal + row * 8);
            s[0] = make_float4(a, b, c, d);
            s[1] = make_float4(r00, r01, 0.f, 0.f);
        }
        __syncthreads();

        // ---------- layer 1: [128x8] @ W1^T -> h1 fragments (ReLU, pack fp16) ----------
        uint32_t ai0, ai1;
        ldmx2(ai0, ai1, uInv + (uint32_t)(warpm + (lane & 15)) * 16u);

        uint32_t aPk[32];                          // layer-2 A frags: 8 k-steps x 4 regs
        #pragma unroll
        for (int s = 0; s < 8; ++s) {
            float dA[4] = {0.f, 0.f, 0.f, 0.f};
            float dB[4] = {0.f, 0.f, 0.f, 0.f};
            mma_k8(dA, ai0, ai1, b1f[2*s]);        // n-tile 2s   (k cols 16s..16s+7)
            mma_k8(dB, ai0, ai1, b1f[2*s+1]);      // n-tile 2s+1 (k cols 16s+8..+15)
            aPk[4*s+0] = pack_h2(fmaxf(dA[0], 0.f), fmaxf(dA[1], 0.f));
            aPk[4*s+1] = pack_h2(fmaxf(dA[2], 0.f), fmaxf(dA[3], 0.f));
            aPk[4*s+2] = pack_h2(fmaxf(dB[0], 0.f), fmaxf(dB[1], 0.f));
            aPk[4*s+3] = pack_h2(fmaxf(dB[2], 0.f), fmaxf(dB[3], 0.f));
        }

        // ---------- layer 2: [128x128] @ W2 -> d2 fragments ----------
        float d2[16][4];
        #pragma unroll
        for (int t = 0; t < 16; ++t) { d2[t][0] = d2[t][1] = d2[t][2] = d2[t][3] = 0.f; }

        #pragma unroll
        for (int s = 0; s < 8; ++s) {
            const uint32_t a0 = aPk[4*s], a1 = aPk[4*s+1], a2 = aPk[4*s+2], a3 = aPk[4*s+3];
            const int c  = 2*s + kSel;
            const int cs = (c & 8) | ((c ^ rowPart) & 7);
            #pragma unroll
            for (int j = 0; j < 8; ++j) {
                uint32_t br0, br1, br2, br3;
                ldmx4(br0, br1, br2, br3,
                      bAddrBase + (uint32_t)(j * 4096) + (uint32_t)cs * 16u);
                mma_k16(d2[2*j],   a0, a1, a2, a3, br0, br1);
                mma_k16(d2[2*j+1], a0, a1, a2, a3, br2, br3);
            }
        }

        // ---------- layer 3 + rotation epilogue ----------
        float acc[8] = {0.f, 0.f, 0.f, 0.f, 0.f, 0.f, 0.f, 0.f};  // rowA o0-3, rowB o0-3
        #pragma unroll
        for (int t = 0; t < 16; ++t) {
            const int n0 = t * 8 + (lane & 3) * 2;
            const float bb0 = sm.b2[n0], bb1 = sm.b2[n0 + 1];
            const float hA0 = fmaxf(d2[t][0] + bb0, 0.f);
            const float hA1 = fmaxf(d2[t][1] + bb1, 0.f);
            const float hB0 = fmaxf(d2[t][2] + bb0, 0.f);
            const float hB1 = fmaxf(d2[t][3] + bb1, 0.f);
            const float4 w0 = reinterpret_cast<const float4*>(sm.w3)[n0];
            const float4 w1 = reinterpret_cast<const float4*>(sm.w3)[n0 + 1];
            acc[0] = fmaf(hA0, w0.x, fmaf(hA1, w1.x, acc[0]));
            acc[1] = fmaf(hA0, w0.y, fmaf(hA1, w1.y, acc[1]));
            acc[2] = fmaf(hA0, w0.z, fmaf(hA1, w1.z, acc[2]));
            acc[3] = fmaf(hA0, w0.w, fmaf(hA1, w1.w, acc[3]));
            acc[4] = fmaf(hB0, w0.x, fmaf(hB1, w1.x, acc[4]));
            acc[5] = fmaf(hB0, w0.y, fmaf(hB1, w1.y, acc[5]));
            acc[6] = fmaf(hB0, w0.z, fmaf(hB1, w1.z, acc[6]));
            acc[7] = fmaf(hB0, w0.w, fmaf(hB1, w1.w, acc[7]));
        }
        #pragma unroll
        for (int i = 0; i < 8; ++i) {
            acc[i] += __shfl_xor_sync(0xffffffffu, acc[i], 1);
            acc[i] += __shfl_xor_sync(0xffffffffu, acc[i], 2);
        }

        if ((lane & 3) == 0) {
            #pragma unroll
            for (int rr = 0; rr < 2; ++rr) {
                const int row  = warpm + (lane >> 2) + rr * 8;
                const int elem = tile * 128 + row;
                if (elem < n) {
                    const float4* s = reinterpret_cast<const float4*>(sm.scal + row * 8);
                    const float4 fv = s[0];
                    const float4 rv = s[1];
                    const float o0 = acc[rr*4+0] + sm.b3[0];
                    const float o1 = acc[rr*4+1] + sm.b3[1];
                    const float o2 = acc[rr*4+2] + sm.b3[2];
                    const float o3 = acc[rr*4+3] + sm.b3[3];
                    const float x00 = o0, x01 = 0.5f * (o1 + o2), x11 = o3;
                    const float r00 = rv.x, r01 = rv.y;
                    float4 ov;
                    ov.x =  r00*x00 + r01*x01 + fv.x;
                    ov.y =  r00*x01 + r01*x11 + fv.y;
                    ov.z = -r01*x00 + r00*x01 + fv.z;
                    ov.w = -r01*x01 + r00*x11 + fv.w;
                    reinterpret_cast<float4*>(out)[elem] = ov;
                }
            }
        }
    }
}

extern "C" void kernel_launch(void* const* d_in, const int* in_sizes, int n_in,
                              void* d_out, int out_size)
{
    const float* F  = (const float*)d_in[0];
    const float* W1 = (const float*)d_in[1];
    const float* b1 = (const float*)d_in[2];
    const float* W2 = (const float*)d_in[3];
    const float* b2 = (const float*)d_in[4];
    const float* W3 = (const float*)d_in[5];
    const float* b3 = (const float*)d_in[6];
    float* out = (float*)d_out;

    const int n = in_sizes[0] / 4;   // number of 2x2 matrices

    defcorr_mma<<<NBLOCKS, NTHREADS>>>(F, W1, b1, W2, b2, W3, b3, out, n);
}